// round 6
// baseline (speedup 1.0000x reference)
#include <cuda_runtime.h>

// FraudDetectionModel R6: single graph node.
//  - Param fold by thread 0 into smem (overlapped with data LDGs),
//    read back once per thread as 7x LDS.128.
//  - 8 rows/thread: halves the param-LDS share of L1tex wavefronts
//    relative to data (R5 analysis: kernel time ~ tracks DRAM%, and
//    DRAM% is throttled by L1tex contention from param reads).
//  - Plain cached ld/st (.cs regressed in R3).

#define BATCH 16777216
#define THREADS 256
#define ROWS_PER_THREAD 8

__device__ __forceinline__ float fast_tanh(float x) {
    float y;
    asm("tanh.approx.f32 %0, %1;" : "=f"(y) : "f"(x));
    return y;
}

// Folded parameter block (28 floats, 16B-aligned):
// [l*6 + 0..3] W'_l (2x2)   [l*6 + 4..5] b'_l   for l = 0..3
// [24:26) wf'   [26] bf'   [27] pad
__global__ void __launch_bounds__(THREADS)
fraud_mlp_kernel(const float4* __restrict__ x,    // [B/2] row pairs
                 float4*       __restrict__ out,  // [B/4] quad outputs
                 const float*  __restrict__ Ws,   // [4,2,2]
                 const float*  __restrict__ bs,   // [4,2]
                 const float*  __restrict__ sc,   // [4,2]
                 const float*  __restrict__ sh,   // [4,2]
                 const float*  __restrict__ Wf,   // [1,2]
                 const float*  __restrict__ bf)   // [1]
{
    __shared__ __align__(16) float p[28];

    const int i = blockIdx.x * blockDim.x + threadIdx.x;

    // 8 rows: 4 front-batched 128-bit loads, issued BEFORE the barrier
    // so the param fold hides under LDG latency.
    float4 xv[4];
#pragma unroll
    for (int k = 0; k < 4; k++) xv[k] = x[4 * i + k];

    if (threadIdx.x == 0) {
        // layer 0 unchanged
        p[0] = __ldg(Ws + 0); p[1] = __ldg(Ws + 1);
        p[2] = __ldg(Ws + 2); p[3] = __ldg(Ws + 3);
        p[4] = __ldg(bs + 0); p[5] = __ldg(bs + 1);

        // layers 1..3: W'_l = W_l * diag(s_{l-1}); b'_l = W_l t_{l-1} + b_l
#pragma unroll
        for (int l = 1; l < 4; l++) {
            const float w00 = __ldg(Ws + l * 4 + 0), w01 = __ldg(Ws + l * 4 + 1);
            const float w10 = __ldg(Ws + l * 4 + 2), w11 = __ldg(Ws + l * 4 + 3);
            const float sp0 = __ldg(sc + (l - 1) * 2 + 0), sp1 = __ldg(sc + (l - 1) * 2 + 1);
            const float tp0 = __ldg(sh + (l - 1) * 2 + 0), tp1 = __ldg(sh + (l - 1) * 2 + 1);
            p[l * 6 + 0] = w00 * sp0;
            p[l * 6 + 1] = w01 * sp1;
            p[l * 6 + 2] = w10 * sp0;
            p[l * 6 + 3] = w11 * sp1;
            p[l * 6 + 4] = fmaf(w00, tp0, fmaf(w01, tp1, __ldg(bs + l * 2 + 0)));
            p[l * 6 + 5] = fmaf(w10, tp0, fmaf(w11, tp1, __ldg(bs + l * 2 + 1)));
        }

        // final: wf' = Wf * diag(s_3); bf' = Wf t_3 + bf
        const float s30 = __ldg(sc + 6), s31 = __ldg(sc + 7);
        const float t30 = __ldg(sh + 6), t31 = __ldg(sh + 7);
        const float f0 = __ldg(Wf + 0), f1 = __ldg(Wf + 1);
        p[24] = f0 * s30;
        p[25] = f1 * s31;
        p[26] = fmaf(f0, t30, fmaf(f1, t31, __ldg(bf)));
        p[27] = 0.0f;
    }
    __syncthreads();

    // Params into registers: 7 broadcast LDS.128.
    float pr[28];
    const float4* pv = reinterpret_cast<const float4*>(p);
#pragma unroll
    for (int k = 0; k < 7; k++) {
        float4 v = pv[k];
        pr[4 * k + 0] = v.x;
        pr[4 * k + 1] = v.y;
        pr[4 * k + 2] = v.z;
        pr[4 * k + 3] = v.w;
    }

    float ha[8], hb[8];
#pragma unroll
    for (int k = 0; k < 4; k++) {
        ha[2 * k + 0] = xv[k].x; hb[2 * k + 0] = xv[k].y;
        ha[2 * k + 1] = xv[k].z; hb[2 * k + 1] = xv[k].w;
    }

#pragma unroll
    for (int l = 0; l < 4; l++) {
        const float w00 = pr[l * 6 + 0], w01 = pr[l * 6 + 1];
        const float w10 = pr[l * 6 + 2], w11 = pr[l * 6 + 3];
        const float b0  = pr[l * 6 + 4], b1  = pr[l * 6 + 5];
#pragma unroll
        for (int r = 0; r < 8; r++) {
            float u0 = fmaf(w00, ha[r], fmaf(w01, hb[r], b0));
            float u1 = fmaf(w10, ha[r], fmaf(w11, hb[r], b1));
            ha[r] = fast_tanh(u0);
            hb[r] = fast_tanh(u1);
        }
    }

    const float wf0 = pr[24], wf1 = pr[25], bff = pr[26];

    float o[8];
#pragma unroll
    for (int r = 0; r < 8; r++)
        o[r] = fmaf(wf0, ha[r], fmaf(wf1, hb[r], bff));

    out[2 * i + 0] = make_float4(o[0], o[1], o[2], o[3]);
    out[2 * i + 1] = make_float4(o[4], o[5], o[6], o[7]);
}

extern "C" void kernel_launch(void* const* d_in, const int* in_sizes, int n_in,
                              void* d_out, int out_size)
{
    const float4* x = (const float4*)d_in[0];
    float4* out = (float4*)d_out;

    const int nthreads = BATCH / ROWS_PER_THREAD;   // 2,097,152
    const int blocks = nthreads / THREADS;          // 8192
    fraud_mlp_kernel<<<blocks, THREADS>>>(
        x, out,
        (const float*)d_in[1], (const float*)d_in[2], (const float*)d_in[3],
        (const float*)d_in[4], (const float*)d_in[5], (const float*)d_in[6]);
}

// round 7
// speedup vs baseline: 1.4932x; 1.4932x over previous
#include <cuda_runtime.h>

// FraudDetectionModel R7: single graph node.
//  - 8 rows/thread, BLOCK-STRIDED: 4 perfectly-coalesced LDG.128
//    (nL=4 each; 8w*4*4=128 < 248 L1tex queue threshold -- R6's
//    thread-contiguous layout had nL=16 -> 512 >> 248, catastrophic).
//  - Outputs as 4 coalesced float2 stores (1 input float4 -> 1 out float2).
//  - Param fold by thread 0 into smem; read per-layer as 2x LDS.128
//    (keeps live regs ~28; R6's upfront 28-reg param block hit 40 regs
//    and dropped occupancy to 68%).

#define BATCH 16777216
#define THREADS 256
#define ROWS_PER_THREAD 8
#define F4_PER_BLOCK (THREADS * ROWS_PER_THREAD / 2)   // 1024

__device__ __forceinline__ float fast_tanh(float x) {
    float y;
    asm("tanh.approx.f32 %0, %1;" : "=f"(y) : "f"(x));
    return y;
}

// smem param layout, 8 floats per layer for clean float4 access:
//   layer l (0..3) at [8l]:  w00 w01 w10 w11 b0 b1 pad pad
//   final at [32]:           wf0 wf1 bf pad
__global__ void __launch_bounds__(THREADS)
fraud_mlp_kernel(const float4* __restrict__ x,    // [B/2] row pairs
                 float2*       __restrict__ out,  // [B/2] row-pair outputs
                 const float*  __restrict__ Ws,   // [4,2,2]
                 const float*  __restrict__ bs,   // [4,2]
                 const float*  __restrict__ sc,   // [4,2]
                 const float*  __restrict__ sh,   // [4,2]
                 const float*  __restrict__ Wf,   // [1,2]
                 const float*  __restrict__ bf)   // [1]
{
    __shared__ __align__(16) float p[36];

    const int base = blockIdx.x * F4_PER_BLOCK + threadIdx.x;

    // 4 perfectly-coalesced, front-batched 128-bit loads (stride 256 float4s).
    float4 xv0 = x[base + 0 * THREADS];
    float4 xv1 = x[base + 1 * THREADS];
    float4 xv2 = x[base + 2 * THREADS];
    float4 xv3 = x[base + 3 * THREADS];

    if (threadIdx.x == 0) {
        // layer 0 unchanged
        p[0] = __ldg(Ws + 0); p[1] = __ldg(Ws + 1);
        p[2] = __ldg(Ws + 2); p[3] = __ldg(Ws + 3);
        p[4] = __ldg(bs + 0); p[5] = __ldg(bs + 1);
        p[6] = 0.f; p[7] = 0.f;

        // layers 1..3: W'_l = W_l * diag(s_{l-1}); b'_l = W_l t_{l-1} + b_l
#pragma unroll
        for (int l = 1; l < 4; l++) {
            const float w00 = __ldg(Ws + l * 4 + 0), w01 = __ldg(Ws + l * 4 + 1);
            const float w10 = __ldg(Ws + l * 4 + 2), w11 = __ldg(Ws + l * 4 + 3);
            const float sp0 = __ldg(sc + (l - 1) * 2 + 0), sp1 = __ldg(sc + (l - 1) * 2 + 1);
            const float tp0 = __ldg(sh + (l - 1) * 2 + 0), tp1 = __ldg(sh + (l - 1) * 2 + 1);
            p[l * 8 + 0] = w00 * sp0;
            p[l * 8 + 1] = w01 * sp1;
            p[l * 8 + 2] = w10 * sp0;
            p[l * 8 + 3] = w11 * sp1;
            p[l * 8 + 4] = fmaf(w00, tp0, fmaf(w01, tp1, __ldg(bs + l * 2 + 0)));
            p[l * 8 + 5] = fmaf(w10, tp0, fmaf(w11, tp1, __ldg(bs + l * 2 + 1)));
            p[l * 8 + 6] = 0.f; p[l * 8 + 7] = 0.f;
        }

        // final: wf' = Wf * diag(s_3); bf' = Wf t_3 + bf
        const float s30 = __ldg(sc + 6), s31 = __ldg(sc + 7);
        const float t30 = __ldg(sh + 6), t31 = __ldg(sh + 7);
        const float f0 = __ldg(Wf + 0), f1 = __ldg(Wf + 1);
        p[32] = f0 * s30;
        p[33] = f1 * s31;
        p[34] = fmaf(f0, t30, fmaf(f1, t31, __ldg(bf)));
        p[35] = 0.0f;
    }
    __syncthreads();

    const float4* pv = reinterpret_cast<const float4*>(p);

    float ha[8], hb[8];
    ha[0] = xv0.x; hb[0] = xv0.y;  ha[1] = xv0.z; hb[1] = xv0.w;
    ha[2] = xv1.x; hb[2] = xv1.y;  ha[3] = xv1.z; hb[3] = xv1.w;
    ha[4] = xv2.x; hb[4] = xv2.y;  ha[5] = xv2.z; hb[5] = xv2.w;
    ha[6] = xv3.x; hb[6] = xv3.y;  ha[7] = xv3.z; hb[7] = xv3.w;

#pragma unroll
    for (int l = 0; l < 4; l++) {
        // per-layer params: 2 broadcast LDS.128 (low live-register pressure)
        const float4 wv = pv[2 * l + 0];   // w00 w01 w10 w11
        const float4 bv = pv[2 * l + 1];   // b0 b1 - -
#pragma unroll
        for (int r = 0; r < 8; r++) {
            float u0 = fmaf(wv.x, ha[r], fmaf(wv.y, hb[r], bv.x));
            float u1 = fmaf(wv.z, ha[r], fmaf(wv.w, hb[r], bv.y));
            ha[r] = fast_tanh(u0);
            hb[r] = fast_tanh(u1);
        }
    }

    const float4 fv = pv[8];   // wf0 wf1 bf -

    // 4 coalesced float2 stores: out float2 index == input float4 index.
    out[base + 0 * THREADS] = make_float2(fmaf(fv.x, ha[0], fmaf(fv.y, hb[0], fv.z)),
                                          fmaf(fv.x, ha[1], fmaf(fv.y, hb[1], fv.z)));
    out[base + 1 * THREADS] = make_float2(fmaf(fv.x, ha[2], fmaf(fv.y, hb[2], fv.z)),
                                          fmaf(fv.x, ha[3], fmaf(fv.y, hb[3], fv.z)));
    out[base + 2 * THREADS] = make_float2(fmaf(fv.x, ha[4], fmaf(fv.y, hb[4], fv.z)),
                                          fmaf(fv.x, ha[5], fmaf(fv.y, hb[5], fv.z)));
    out[base + 3 * THREADS] = make_float2(fmaf(fv.x, ha[6], fmaf(fv.y, hb[6], fv.z)),
                                          fmaf(fv.x, ha[7], fmaf(fv.y, hb[7], fv.z)));
}

extern "C" void kernel_launch(void* const* d_in, const int* in_sizes, int n_in,
                              void* d_out, int out_size)
{
    const float4* x = (const float4*)d_in[0];
    float2* out = (float2*)d_out;

    const int nthreads = BATCH / ROWS_PER_THREAD;   // 2,097,152
    const int blocks = nthreads / THREADS;          // 8192
    fraud_mlp_kernel<<<blocks, THREADS>>>(
        x, out,
        (const float*)d_in[1], (const float*)d_in[2], (const float*)d_in[3],
        (const float*)d_in[4], (const float*)d_in[5], (const float*)d_in[6]);
}